// round 1
// baseline (speedup 1.0000x reference)
#include <cuda_runtime.h>
#include <math.h>

#define NB 32
#define NT 1024
#define NE 256
#define NH 4
#define NHD 64
#define NP 32
#define NM (NB*NT)

// ---- scratch (static device globals; no runtime allocation) ----
__device__ float g_h  [(size_t)NM*NE];      // input-proj output   [32768,256]
__device__ float g_qkv[(size_t)NM*3*NE];    // qkv                 [32768,768]
__device__ float g_ctx[(size_t)NM*NE];      // attention context   [32768,256]
__device__ float g_ao [(size_t)NM*NE];      // attn out proj       [32768,256]
__device__ float g_bs [NM];                 // boundary scores     [32768]
__device__ int   g_pid[NM];                 // patch ids           [32768]
__device__ float g_pe [NB*NP*NE];           // pooled patch means  [1024,256]

// ============================================================================
// C[M,N] = A[M,K] @ W[N,K]^T + bias      (M%64==0, N%64==0, K%16==0)
// 64x64 block tile, BK=16, 256 threads, 4x4 register tile per thread.
// ============================================================================
__global__ __launch_bounds__(256) void gemm_bias_kernel(
    const float* __restrict__ A, const float* __restrict__ W,
    const float* __restrict__ bias, float* __restrict__ C,
    int Mdim, int Ndim, int Kdim)
{
    __shared__ float As[16][68];   // [k][m]
    __shared__ float Bs[16][68];   // [k][n]
    const int tid = threadIdx.x;
    const int tx = tid & 15, ty = tid >> 4;
    const int bm = blockIdx.y << 6;
    const int bn = blockIdx.x << 6;
    const int lr = tid >> 2;          // 0..63
    const int lc = (tid & 3) << 2;    // 0,4,8,12

    float acc[4][4];
#pragma unroll
    for (int i = 0; i < 4; i++)
#pragma unroll
        for (int j = 0; j < 4; j++) acc[i][j] = 0.f;

    const float* Ap = A + (size_t)(bm + lr) * Kdim + lc;
    const float* Wp = W + (size_t)(bn + lr) * Kdim + lc;

    for (int k0 = 0; k0 < Kdim; k0 += 16) {
        float4 a = *(const float4*)(Ap + k0);
        float4 w = *(const float4*)(Wp + k0);
        As[lc+0][lr]=a.x; As[lc+1][lr]=a.y; As[lc+2][lr]=a.z; As[lc+3][lr]=a.w;
        Bs[lc+0][lr]=w.x; Bs[lc+1][lr]=w.y; Bs[lc+2][lr]=w.z; Bs[lc+3][lr]=w.w;
        __syncthreads();
#pragma unroll
        for (int kk = 0; kk < 16; kk++) {
            float4 ra = *(const float4*)&As[kk][ty<<2];
            float4 rb = *(const float4*)&Bs[kk][tx<<2];
            float av[4] = {ra.x,ra.y,ra.z,ra.w};
            float bv[4] = {rb.x,rb.y,rb.z,rb.w};
#pragma unroll
            for (int i = 0; i < 4; i++)
#pragma unroll
                for (int j = 0; j < 4; j++) acc[i][j] += av[i]*bv[j];
        }
        __syncthreads();
    }
    const int cbase = bn + (tx<<2);
    float4 bb = *(const float4*)(bias + cbase);
#pragma unroll
    for (int i = 0; i < 4; i++) {
        int r = bm + (ty<<2) + i;
        float4 o;
        o.x = acc[i][0]+bb.x; o.y = acc[i][1]+bb.y;
        o.z = acc[i][2]+bb.z; o.w = acc[i][3]+bb.w;
        *(float4*)(C + (size_t)r*Ndim + cbase) = o;
    }
}

// ============================================================================
// Flash attention, fp32. One block = one (b,h) x 64 query rows.
// BQ=64, BKV=32, HD=64, 256 threads (16x16). 44KB static smem.
// qkv layout: row (b*T+t)*768, q @ h*64, k @ 256+h*64, v @ 512+h*64.
// ============================================================================
__global__ __launch_bounds__(256) void flash_kernel(
    const float* __restrict__ qkv, float* __restrict__ ctx)
{
    __shared__ float Qs [64][68];   // [row][d]
    __shared__ float KsT[64][33];   // [d][key]  (transposed for conflict-free S reads)
    __shared__ float Vs [32][68];   // [key][d]
    __shared__ float Ps [64][36];   // [row][key]

    const int tid = threadIdx.x;
    const int tx = tid & 15, ty = tid >> 4;
    const int qb = blockIdx.x;            // 0..15
    const int bh = blockIdx.y;            // 0..127
    const int b = bh >> 2, h = bh & 3;

    const float* base = qkv + (size_t)b * NT * (3*NE);
    const int qoff = h * NHD;
    const int koff = NE + h * NHD;
    const int voff = 2*NE + h * NHD;
    const int qstart = qb << 6;

    // load Q tile (pre-scaled by 1/sqrt(HD) = 0.125)
#pragma unroll
    for (int it = 0; it < 4; it++) {
        int idx = it*256 + tid;
        int r  = idx >> 4;
        int c4 = (idx & 15) << 2;
        float4 v = *(const float4*)(base + (size_t)(qstart + r)*(3*NE) + qoff + c4);
        Qs[r][c4+0] = v.x*0.125f; Qs[r][c4+1] = v.y*0.125f;
        Qs[r][c4+2] = v.z*0.125f; Qs[r][c4+3] = v.w*0.125f;
    }

    float m[4], l[4], o[4][4];
#pragma unroll
    for (int i = 0; i < 4; i++) {
        m[i] = -1e30f; l[i] = 0.f;
#pragma unroll
        for (int j = 0; j < 4; j++) o[i][j] = 0.f;
    }

    for (int kb = 0; kb < 32; kb++) {
        __syncthreads();   // prior-iter smem reads done (and Q stores on iter 0)
        // load K (transposed) and V tiles: 32 rows x 64 d
#pragma unroll
        for (int it = 0; it < 2; it++) {
            int idx = it*256 + tid;
            int r  = idx >> 4;
            int c4 = (idx & 15) << 2;
            size_t ra = (size_t)(kb*32 + r) * (3*NE);
            float4 kv = *(const float4*)(base + ra + koff + c4);
            KsT[c4+0][r]=kv.x; KsT[c4+1][r]=kv.y; KsT[c4+2][r]=kv.z; KsT[c4+3][r]=kv.w;
            float4 vv = *(const float4*)(base + ra + voff + c4);
            *(float4*)&Vs[r][c4] = vv;
        }
        __syncthreads();

        // S tile: rows ty*4+i (4), keys tx*2+j (2)
        float s[4][2];
#pragma unroll
        for (int i = 0; i < 4; i++) { s[i][0]=0.f; s[i][1]=0.f; }
#pragma unroll 4
        for (int d = 0; d < 64; d++) {
            float kf0 = KsT[d][(tx<<1)];
            float kf1 = KsT[d][(tx<<1)+1];
#pragma unroll
            for (int i = 0; i < 4; i++) {
                float qf = Qs[(ty<<2)+i][d];
                s[i][0] += qf*kf0;
                s[i][1] += qf*kf1;
            }
        }

        // online softmax (reduce across the 16 tx lanes of each half-warp)
#pragma unroll
        for (int i = 0; i < 4; i++) {
            float mx = fmaxf(s[i][0], s[i][1]);
#pragma unroll
            for (int off = 1; off < 16; off <<= 1)
                mx = fmaxf(mx, __shfl_xor_sync(0xffffffffu, mx, off));
            float mnew = fmaxf(m[i], mx);
            float corr = __expf(m[i] - mnew);
            float p0 = __expf(s[i][0] - mnew);
            float p1 = __expf(s[i][1] - mnew);
            float ls = p0 + p1;
#pragma unroll
            for (int off = 1; off < 16; off <<= 1)
                ls += __shfl_xor_sync(0xffffffffu, ls, off);
            l[i] = l[i]*corr + ls;
            m[i] = mnew;
#pragma unroll
            for (int j = 0; j < 4; j++) o[i][j] *= corr;
            Ps[(ty<<2)+i][(tx<<1)]   = p0;
            Ps[(ty<<2)+i][(tx<<1)+1] = p1;
        }
        __syncthreads();

        // O += P @ V : rows ty*4+i, d-cols tx*4+j
#pragma unroll 4
        for (int kk = 0; kk < 32; kk++) {
            float4 vv = *(const float4*)&Vs[kk][tx<<2];
            float vf[4] = {vv.x, vv.y, vv.z, vv.w};
#pragma unroll
            for (int i = 0; i < 4; i++) {
                float pf = Ps[(ty<<2)+i][kk];
#pragma unroll
                for (int j = 0; j < 4; j++) o[i][j] += pf*vf[j];
            }
        }
    }

#pragma unroll
    for (int i = 0; i < 4; i++) {
        int r = (ty<<2) + i;
        float inv = 1.f / l[i];
        float* outp = ctx + ((size_t)(b*NT) + qstart + r) * NE + h*NHD + (tx<<2);
        *(float4*)outp = make_float4(o[i][0]*inv, o[i][1]*inv, o[i][2]*inv, o[i][3]*inv);
    }
}

// ============================================================================
// Boundary MLP: sigmoid(relu(ao @ w1^T + b1) @ w2^T + b2). One warp per row;
// each lane owns one of the 32 hidden units.
// ============================================================================
__global__ __launch_bounds__(256) void boundary_kernel(
    const float* __restrict__ ao, const float* __restrict__ w1,
    const float* __restrict__ b1, const float* __restrict__ w2,
    const float* __restrict__ b2, float* __restrict__ bscore)
{
    int row  = (blockIdx.x << 3) + (threadIdx.x >> 5);
    int lane = threadIdx.x & 31;
    const float4* a = (const float4*)(ao + (size_t)row * NE);
    const float4* w = (const float4*)(w1 + lane * NE);
    float acc = 0.f;
#pragma unroll 16
    for (int d = 0; d < 64; d++) {
        float4 av = a[d], wv = w[d];
        acc += av.x*wv.x + av.y*wv.y + av.z*wv.z + av.w*wv.w;
    }
    float hh = fmaxf(acc + b1[lane], 0.f);
    float s = hh * w2[lane];
#pragma unroll
    for (int off = 16; off; off >>= 1)
        s += __shfl_xor_sync(0xffffffffu, s, off);
    if (lane == 0)
        bscore[row] = 1.f / (1.f + expf(-(s + b2[0])));
}

// ============================================================================
// Per-batch inclusive cumsum (double precision to track the reference fp32
// scan closely; pid = floor is discontinuous), normalize, patch id.
// ============================================================================
__global__ __launch_bounds__(1024) void scan_kernel(
    const float* __restrict__ bscore, int* __restrict__ pid)
{
    __shared__ double sa[1024], sb[1024];
    int b = blockIdx.x, t = threadIdx.x;
    sa[t] = (double)bscore[b*NT + t];
    __syncthreads();
    double* src = sa; double* dst = sb;
#pragma unroll
    for (int off = 1; off < 1024; off <<= 1) {
        double v = src[t];
        if (t >= off) v += src[t - off];
        dst[t] = v;
        __syncthreads();
        double* tmp = src; src = dst; dst = tmp;
    }
    double total = src[1023] + 1e-6;
    double cbp = src[t] / total;
    int p = (int)floor(cbp * (double)NP);
    if (p > NP-1) p = NP-1;
    if (p < 0) p = 0;
    pid[b*NT + t] = p;
}

__device__ __forceinline__ int lower_bound_dev(const int* a, int n, int key) {
    int lo = 0, hi = n;
    while (lo < hi) { int mid = (lo + hi) >> 1; if (a[mid] < key) lo = mid + 1; else hi = mid; }
    return lo;
}

// ============================================================================
// Segment-mean pooling. pid is monotone non-decreasing per batch (cumsum of
// positive sigmoids), so each patch is a contiguous t-range: binary search
// the bounds, sum coalesced rows. No atomics, no init pass. Empty patch -> 0.
// One block per (b,p); 256 threads = E columns.
// ============================================================================
__global__ __launch_bounds__(256) void pool_kernel(
    const float* __restrict__ ao, const int* __restrict__ pid,
    float* __restrict__ pe)
{
    int bp = blockIdx.x;
    int b = bp >> 5, p = bp & 31;
    const int* pa = pid + b*NT;
    int s = lower_bound_dev(pa, NT, p);
    int e = lower_bound_dev(pa, NT, p+1);
    float inv = 1.f / (float)((e - s) > 0 ? (e - s) : 1);
    int col = threadIdx.x;
    float sum = 0.f;
    for (int t = s; t < e; t++)
        sum += ao[((size_t)(b*NT) + t) * NE + col];
    pe[(size_t)bp * NE + col] = sum * inv;
}

// ============================================================================
extern "C" void kernel_launch(void* const* d_in, const int* in_sizes, int n_in,
                              void* d_out, int out_size)
{
    (void)in_sizes; (void)n_in; (void)out_size;
    const float* x        = (const float*)d_in[0];
    const float* ip_w     = (const float*)d_in[1];
    const float* ip_b     = (const float*)d_in[2];
    const float* inproj_w = (const float*)d_in[3];
    const float* inproj_b = (const float*)d_in[4];
    const float* out_w    = (const float*)d_in[5];
    const float* out_b    = (const float*)d_in[6];
    const float* bp_w1    = (const float*)d_in[7];
    const float* bp_b1    = (const float*)d_in[8];
    const float* bp_w2    = (const float*)d_in[9];
    const float* bp_b2    = (const float*)d_in[10];
    const float* pr_w     = (const float*)d_in[11];
    const float* pr_b     = (const float*)d_in[12];
    float* out = (float*)d_out;

    void* p;
    float *h, *qkv, *ctx, *ao, *bs, *pe; int* pid;
    cudaGetSymbolAddress(&p, g_h);   h   = (float*)p;
    cudaGetSymbolAddress(&p, g_qkv); qkv = (float*)p;
    cudaGetSymbolAddress(&p, g_ctx); ctx = (float*)p;
    cudaGetSymbolAddress(&p, g_ao);  ao  = (float*)p;
    cudaGetSymbolAddress(&p, g_bs);  bs  = (float*)p;
    cudaGetSymbolAddress(&p, g_pid); pid = (int*)p;
    cudaGetSymbolAddress(&p, g_pe);  pe  = (float*)p;

    dim3 blk(256);
    // 1) input projection: [32768,32] -> [32768,256]
    gemm_bias_kernel<<<dim3(NE/64, NM/64), blk>>>(x, ip_w, ip_b, h, NM, NE, 32);
    // 2) qkv projection: [32768,256] -> [32768,768]
    gemm_bias_kernel<<<dim3(3*NE/64, NM/64), blk>>>(h, inproj_w, inproj_b, qkv, NM, 3*NE, NE);
    // 3) attention -> ctx
    flash_kernel<<<dim3(NT/64, NB*NH), blk>>>(qkv, ctx);
    // 4) out projection
    gemm_bias_kernel<<<dim3(NE/64, NM/64), blk>>>(ctx, out_w, out_b, ao, NM, NE, NE);
    // 5) boundary scores
    boundary_kernel<<<NM/8, blk>>>(ao, bp_w1, bp_b1, bp_w2, bp_b2, bs);
    // 6) cumsum + patch ids
    scan_kernel<<<NB, NT>>>(bs, pid);
    // 7) segment-mean pooling
    pool_kernel<<<NB*NP, NE>>>(ao, pid, pe);
    // 8) patch projection -> output [32,32,256]
    gemm_bias_kernel<<<dim3(NE/64, (NB*NP)/64), blk>>>(pe, pr_w, pr_b, out, NB*NP, NE, NE);
}